// round 15
// baseline (speedup 1.0000x reference)
#include <cuda_runtime.h>
#include <cuda_bf16.h>
#include <cstring>

typedef unsigned long long ull;

#define BB 8
#define LL 4096
#define DX 128
#define BL (BB*LL)
#define GRIDN 128
#define SLICES 16
#define SLEN (LL/SLICES)
#define ST 136            // padded bf16 row stride (272B; conflict-free for ldmatrix)

// ---------------- scratch ----------------
__device__ __align__(16) float g_v1[DX], g_u1[DX], g_u2[DX];
__device__ float g_cconst;
__device__ float g_logits[BL], g_d1[BL], g_d2[BL];
__device__ float g_si[BL], g_sjc[BL];
__device__ float g_invZ[BL], g_S[BL];
__device__ float g_Mpart[GRIDN*10], g_Fpart[GRIDN*10];
__device__ float g_psum[GRIDN];
__device__ unsigned g_lmax[BB];
__device__ unsigned g_msi, g_msjc;
__device__ ull g_barcnt = 0;

// pre-transposed bf16-split weight images: [n][k] row-major, stride ST
__device__ __align__(16) __nv_bfloat16 g_w1hi[128*ST], g_w1lo[128*ST];
__device__ __align__(16) __nv_bfloat16 g_w2hi[128*ST], g_w2lo[128*ST];

// ---------------- exp(sigmoid(t)) Taylor deg-9, valid |t|<=1 ----------------
#define P0f  1.64872127f
#define P1f  0.412180318f
#define P2f  0.0515225397f
#define P3f (-0.03005490f)
#define P4f (-0.00831874f)
#define P5f  0.00237489f
#define P6f  0.00112763f
#define P7f (-1.56355e-4f)
#define P8f (-1.38606e-4f)
#define P9f  5.4551e-6f

__constant__ float c_P[10] = {P0f,P1f,P2f,P3f,P4f,P5f,P6f,P7f,P8f,P9f};
__constant__ float c_BIN[10][10] = {
    {1,0,0,0,0,0,0,0,0,0},
    {1,1,0,0,0,0,0,0,0,0},
    {1,2,1,0,0,0,0,0,0,0},
    {1,3,3,1,0,0,0,0,0,0},
    {1,4,6,4,1,0,0,0,0,0},
    {1,5,10,10,5,1,0,0,0,0},
    {1,6,15,20,15,6,1,0,0,0},
    {1,7,21,35,35,21,7,1,0,0},
    {1,8,28,56,70,56,28,8,1,0},
    {1,9,36,84,126,126,84,36,9,1},
};

__device__ __forceinline__ float fpoly(float t){
    float r = P9f;
    r = fmaf(r,t,P8f); r = fmaf(r,t,P7f); r = fmaf(r,t,P6f);
    r = fmaf(r,t,P5f); r = fmaf(r,t,P4f); r = fmaf(r,t,P3f);
    r = fmaf(r,t,P2f); r = fmaf(r,t,P1f); r = fmaf(r,t,P0f);
    return r;
}

__device__ __forceinline__ float ex2a(float x){ float r; asm("ex2.approx.ftz.f32 %0,%1;":"=f"(r):"f"(x)); return r; }
__device__ __forceinline__ float rcpa(float x){ float r; asm("rcp.approx.ftz.f32 %0,%1;":"=f"(r):"f"(x)); return r; }
__device__ __forceinline__ float fsig(float t){
    const float L2E = 1.44269504088896f;
    float e = ex2a(t * -L2E);
    float s = rcpa(1.0f + e);
    return ex2a(s * L2E);
}

__device__ __forceinline__ bool poly_ok(){
    return (__uint_as_float(g_msi) + __uint_as_float(g_msjc)) <= 1.0f;
}

__device__ __forceinline__ unsigned fkey(float f){
    unsigned u = __float_as_uint(f);
    return (u & 0x80000000u) ? ~u : (u | 0x80000000u);
}
__device__ __forceinline__ float funkey(unsigned k){
    unsigned u = (k & 0x80000000u) ? (k ^ 0x80000000u) : ~k;
    return __uint_as_float(u);
}

__device__ __forceinline__ float wradd(float v){
    #pragma unroll
    for (int o=16;o;o>>=1) v += __shfl_xor_sync(0xffffffffu, v, o);
    return v;
}

// ---------------- bf16 helpers ----------------
__device__ __forceinline__ unsigned pack_split_hi(float a, float b, unsigned &plo){
    __nv_bfloat16 ha = __float2bfloat16(a);
    __nv_bfloat16 la = __float2bfloat16(a - __bfloat162float(ha));
    __nv_bfloat16 hb = __float2bfloat16(b);
    __nv_bfloat16 lb = __float2bfloat16(b - __bfloat162float(hb));
    __nv_bfloat162 th; th.x = ha; th.y = hb;
    __nv_bfloat162 tl; tl.x = la; tl.y = lb;
    unsigned uh, ul;
    memcpy(&uh, &th, 4); memcpy(&ul, &tl, 4);
    plo = ul;
    return uh;
}

// NON-volatile: pure register op; lets ptxas software-pipeline MMAs under ldmatrix
__device__ __forceinline__ void mma16816(float c[4],
        unsigned a0, unsigned a1, unsigned a2, unsigned a3,
        unsigned b0, unsigned b1)
{
    asm("mma.sync.aligned.m16n8k16.row.col.f32.bf16.bf16.f32 "
        "{%0,%1,%2,%3}, {%4,%5,%6,%7}, {%8,%9}, {%0,%1,%2,%3};"
        : "+f"(c[0]), "+f"(c[1]), "+f"(c[2]), "+f"(c[3])
        : "r"(a0), "r"(a1), "r"(a2), "r"(a3), "r"(b0), "r"(b1));
}

__device__ __forceinline__ void ldm_x4(unsigned r[4], unsigned addr){
    asm volatile("ldmatrix.sync.aligned.m8n8.x4.shared.b16 {%0,%1,%2,%3}, [%4];"
        : "=r"(r[0]), "=r"(r[1]), "=r"(r[2]), "=r"(r[3]) : "r"(addr));
}

// ---------------- grid barrier ----------------
__device__ __forceinline__ void gsync(){
    __syncthreads();
    if (threadIdx.x == 0){
        __threadfence();
        ull t = atomicAdd(&g_barcnt, 1ull);
        ull target = (t/GRIDN + 1ull) * (ull)GRIDN;
        while (*((volatile ull*)&g_barcnt) < target) __nanosleep(64);
        __threadfence();
    }
    __syncthreads();
}

// ================= MEGA KERNEL =================
__global__ void __launch_bounds__(512) kmega(
        const float* __restrict__ x,
        const float* __restrict__ W1,  const float* __restrict__ wt_w,
        const float* __restrict__ Wsa1,const float* __restrict__ Wsa2,
        const float* __restrict__ wsat_w, const float* __restrict__ wsat_b,
        const float* __restrict__ bsa1,
        const float* __restrict__ pw1, const float* __restrict__ pw2)
{
    __shared__ __align__(16) float sbuf[8192];
    __shared__ float sred[16];
    __shared__ float smom[8][10];
    __shared__ float sE[10];

    int tid  = threadIdx.x;
    int lane = tid & 31, wid = tid >> 5;
    int bk = blockIdx.x;
    int b  = bk >> 4;
    int s  = bk & 15;

    // ---------- phase 0: prep + weight image build ----------
    if (bk < 3){
        float* vec = sbuf;
        float* sp  = sbuf + 128;
        if (tid < DX) vec[tid] = (bk==0) ? wt_w[tid] : wsat_w[tid];
        __syncthreads();
        const float* W = (bk==0)?W1:(bk==1)?Wsa1:Wsa2;
        int d = tid & 127, p = tid >> 7;
        float a = 0.f;
        #pragma unroll 8
        for (int e=p*32; e<p*32+32; e++) a = fmaf(W[d*DX+e], vec[e], a);
        sp[p*DX + d] = a;
        __syncthreads();
        if (tid < DX){
            float t = (sp[tid]+sp[DX+tid]) + (sp[2*DX+tid]+sp[3*DX+tid]);
            float* dst = (bk==0)?g_v1:(bk==1)?g_u1:g_u2;
            dst[tid] = t;
        }
    } else if (bk == 3){
        if (tid < DX) sbuf[tid] = bsa1[tid]*wsat_w[tid];
        __syncthreads();
        for (int o=64;o;o>>=1){ if(tid<o) sbuf[tid]+=sbuf[tid+o]; __syncthreads(); }
        if (tid==0){ g_cconst = sbuf[0] + wsat_b[0]; g_msi=0u; g_msjc=0u; }
        if (tid < BB) g_lmax[tid] = 0u;
    } else if (bk == 4 || bk == 5){
        const float* W = (bk==4) ? pw1 : pw2;
        __nv_bfloat16* ih = (bk==4) ? g_w1hi : g_w2hi;
        __nv_bfloat16* il = (bk==4) ? g_w1lo : g_w2lo;
        for (int idx=tid; idx<16384; idx+=512){
            int k = idx & 127, n = idx >> 7;
            float v = W[k*DX + n];
            __nv_bfloat16 h = __float2bfloat16(v);
            __nv_bfloat16 l = __float2bfloat16(v - __bfloat162float(h));
            ih[n*ST + k] = h;
            il[n*ST + k] = l;
        }
    }
    gsync();

    // ---------- phase 1: per-row dots + block logit max ----------
    {
        float4 av = ((const float4*)g_v1)[lane];
        float4 bv = ((const float4*)g_u1)[lane];
        float4 cv = ((const float4*)g_u2)[lane];
        int rowbase = bk*SLEN + wid*16;
        float lmax = -1e30f;
        #pragma unroll 2
        for (int r=0;r<16;r++){
            int row = rowbase + r;
            float4 xv = ((const float4*)x)[row*32 + lane];
            float s0 = xv.x*av.x + xv.y*av.y + xv.z*av.z + xv.w*av.w;
            float s1 = xv.x*bv.x + xv.y*bv.y + xv.z*bv.z + xv.w*bv.w;
            float s2 = xv.x*cv.x + xv.y*cv.y + xv.z*cv.z + xv.w*cv.w;
            #pragma unroll
            for (int o=16;o;o>>=1){
                s0 += __shfl_down_sync(0xffffffffu, s0, o);
                s1 += __shfl_down_sync(0xffffffffu, s1, o);
                s2 += __shfl_down_sync(0xffffffffu, s2, o);
            }
            if (lane==0){
                g_logits[row]=s0; g_d1[row]=s1; g_d2[row]=s2;
                lmax = fmaxf(lmax, s0);
            }
        }
        if (lane==0) sred[wid] = lmax;
        __syncthreads();
        if (tid==0){
            float m = sred[0];
            #pragma unroll
            for (int w=1;w<16;w++) m = fmaxf(m, sred[w]);
            atomicMax(&g_lmax[b], fkey(m));
        }
    }
    gsync();

    // ---------- phase 2: partial softmax sums ----------
    {
        float m = funkey(g_lmax[b]);
        if (tid < SLEN){
            float v = __expf(g_logits[b*LL + s*SLEN + tid] - m);
            v = wradd(v);
            if (lane==0) sred[wid] = v;
        }
        __syncthreads();
        if (tid==0){
            float t = 0.f;
            #pragma unroll
            for (int w=0;w<8;w++) t += sred[w];
            g_psum[bk] = t;
        }
    }
    gsync();

    // ---------- phase 3: si/sjc + ranges + partial sjc-moments ----------
    {
        float m = funkey(g_lmax[b]);
        float t = 0.f;
        #pragma unroll
        for (int k=0;k<SLICES;k++) t += g_psum[b*SLICES+k];
        float inv = 1.0f/t;
        float cc = g_cconst;
        if (tid < SLEN){
            int idx = b*LL + s*SLEN + tid;
            float p = __expf(g_logits[idx]-m)*inv;
            float si  = p*g_d1[idx];
            float sjc = fmaf(p, g_d2[idx], cc);
            g_si[idx]=si; g_sjc[idx]=sjc;
            float rs = fabsf(si), rj = fabsf(sjc);
            #pragma unroll
            for (int o=16;o;o>>=1){
                rs = fmaxf(rs, __shfl_xor_sync(0xffffffffu, rs, o));
                rj = fmaxf(rj, __shfl_xor_sync(0xffffffffu, rj, o));
            }
            if (lane==0){
                atomicMax(&g_msi,  __float_as_uint(rs));
                atomicMax(&g_msjc, __float_as_uint(rj));
            }
            float pw = 1.f;
            #pragma unroll
            for (int k=0;k<10;k++){
                float v = wradd(pw);
                if (lane==0) smom[wid][k]=v;
                pw *= sjc;
            }
        }
        __syncthreads();
        if (tid < 10){
            float acc = 0.f;
            #pragma unroll
            for (int w=0;w<8;w++) acc += smom[w][tid];
            g_Mpart[bk*10 + tid] = acc;
        }
    }
    gsync();

    bool pok = poly_ok();

    if (pok){
        // ---------- phase 4: invZ + partial invZ-weighted si-moments ----------
        if (tid < 10){
            float M[10];
            #pragma unroll
            for (int mi=0;mi<10;mi++){
                float acc = 0.f;
                #pragma unroll
                for (int ss=0;ss<SLICES;ss++) acc += g_Mpart[(b*SLICES+ss)*10 + mi];
                M[mi] = acc;
            }
            float e = 0.f;
            for (int mi=0; tid+mi<10; mi++)
                e = fmaf(c_P[tid+mi]*c_BIN[tid+mi][tid], M[mi], e);
            sE[tid] = e;
        }
        __syncthreads();
        if (tid < SLEN){
            int idx = b*LL + s*SLEN + tid;
            float si = g_si[idx], sjc = g_sjc[idx];
            float z = sE[9];
            #pragma unroll
            for (int k=8;k>=0;k--) z = fmaf(z, si, sE[k]);
            z -= fpoly(si + sjc);
            float w = 1.0f / z;
            g_invZ[idx] = w;
            float pw = w;
            #pragma unroll
            for (int k=0;k<10;k++){
                float v = wradd(pw);
                if (lane==0) smom[wid][k]=v;
                pw *= si;
            }
        }
        __syncthreads();
        if (tid < 10){
            float acc = 0.f;
            #pragma unroll
            for (int w=0;w<8;w++) acc += smom[w][tid];
            g_Fpart[bk*10 + tid] = acc;
        }
    } else {
        // ---------- fallback: full O(L^2) row/col sums ----------
        {
            for (int k=tid;k<LL;k+=512) sbuf[k] = g_sjc[b*LL+k];
            __syncthreads();
            int row = b*LL + s*SLEN + (tid>>1);
            int half = tid & 1;
            float si = g_si[row];
            float a = 0.f;
            for (int j=half*2048; j<half*2048+2048; j++) a += fsig(si + sbuf[j]);
            a += __shfl_xor_sync(0xffffffffu, a, 1);
            if (half==0){
                float Z = a - fsig(si + g_sjc[row]);
                g_invZ[row] = 1.0f / Z;
            }
        }
        gsync();
        {
            float* s_si = sbuf;
            float* s_wz = sbuf + 4096;
            for (int k=tid;k<LL;k+=512){ s_si[k]=g_si[b*LL+k]; s_wz[k]=g_invZ[b*LL+k]; }
            __syncthreads();
            int col = b*LL + s*SLEN + (tid>>1);
            int half = tid & 1;
            float sj = g_sjc[col];
            float a = 0.f;
            for (int i=half*2048; i<half*2048+2048; i++)
                a = fmaf(fsig(sj + s_si[i]), s_wz[i], a);
            a += __shfl_xor_sync(0xffffffffu, a, 1);
            if (half==0)
                g_S[col] = a - fsig(g_si[col] + sj) * g_invZ[col];
        }
    }
}

// ================= kffn: persistent, 512 threads, warp = 16 rows x 64 cols =================
#define IMGB (128*ST*2)
#define WH1_OFF 4096u
#define WL1_OFF (4096u + IMGB)
#define WH2_OFF (4096u + 2*IMGB)
#define WL2_OFF (4096u + 3*IMGB)
#define AH_OFF  (4096u + 4*IMGB)
#define AL_OFF  (4096u + 5*IMGB)
#define KFFN_SMEM (4096 + 6*IMGB)

__device__ __forceinline__ void mma_stage_ldm(
        unsigned ah_base, unsigned al_base,
        unsigned wh_base, unsigned wl_base,
        float acc[8][4])
{
    #pragma unroll
    for (int nt=0;nt<8;nt++){
        acc[nt][0]=0.f; acc[nt][1]=0.f; acc[nt][2]=0.f; acc[nt][3]=0.f;
    }
    #pragma unroll
    for (int k=0;k<8;k++){
        unsigned kb = k*32;
        unsigned ah[4], al[4];
        ldm_x4(ah, ah_base + kb);
        ldm_x4(al, al_base + kb);
        #pragma unroll
        for (int ntp=0;ntp<4;ntp++){
            unsigned pb = ntp*16*(ST*2) + kb;
            unsigned bh[4], bl[4];
            ldm_x4(bh, wh_base + pb);
            ldm_x4(bl, wl_base + pb);
            int n0 = 2*ntp, n1 = 2*ntp+1;
            mma16816(acc[n0], ah[0],ah[1],ah[2],ah[3], bh[0],bh[1]);
            mma16816(acc[n1], ah[0],ah[1],ah[2],ah[3], bh[2],bh[3]);
            mma16816(acc[n0], ah[0],ah[1],ah[2],ah[3], bl[0],bl[1]);
            mma16816(acc[n1], ah[0],ah[1],ah[2],ah[3], bl[2],bl[3]);
            mma16816(acc[n0], al[0],al[1],al[2],al[3], bh[0],bh[1]);
            mma16816(acc[n1], al[0],al[1],al[2],al[3], bh[2],bh[3]);
        }
    }
}

__global__ void __launch_bounds__(512) kffn(const float* __restrict__ x,
        const float* __restrict__ b1, const float* __restrict__ b2,
        const float* __restrict__ lng, const float* __restrict__ lnb,
        float* __restrict__ out)
{
    extern __shared__ __align__(16) char smc[];
    unsigned sb;
    asm("{ .reg .u64 t; cvta.to.shared.u64 t, %1; cvt.u32.u64 %0, t; }" : "=r"(sb) : "l"(smc));

    float*  sS  = (float*)smc;            // 128 floats
    float*  sF  = (float*)(smc + 512);    // 10 floats
    float2* sLN = (float2*)(smc + 1024);  // 128 rows x 2 halves (2KB)
    __nv_bfloat16* Ah = (__nv_bfloat16*)(smc + AH_OFF);
    __nv_bfloat16* Al = (__nv_bfloat16*)(smc + AL_OFF);

    int tid = threadIdx.x;
    int lane = tid & 31, w = tid >> 5;
    int rw = (w & 7) * 16;
    int ch = w >> 3;
    int cb = ch * 64;
    int b = (blockIdx.x * 256) >> 12;
    bool pok = poly_ok();

    if (pok && tid < 10){
        float M[10];
        #pragma unroll
        for (int mi=0;mi<10;mi++){
            float acc = 0.f;
            #pragma unroll
            for (int ss=0;ss<SLICES;ss++) acc += g_Fpart[(b*SLICES+ss)*10 + mi];
            M[mi] = acc;
        }
        float e = 0.f;
        for (int mi=0; tid+mi<10; mi++)
            e = fmaf(c_P[tid+mi]*c_BIN[tid+mi][tid], M[mi], e);
        sF[tid] = e;
    }
    {
        const float4* s1 = (const float4*)g_w1hi;
        const float4* s2 = (const float4*)g_w1lo;
        const float4* s3 = (const float4*)g_w2hi;
        const float4* s4 = (const float4*)g_w2lo;
        float4* d1 = (float4*)(smc + WH1_OFF);
        float4* d2 = (float4*)(smc + WL1_OFF);
        float4* d3 = (float4*)(smc + WH2_OFF);
        float4* d4 = (float4*)(smc + WL2_OFF);
        for (int k=tid; k<IMGB/16; k+=512){ d1[k]=s1[k]; d2[k]=s2[k]; d3[k]=s3[k]; d4[k]=s4[k]; }
    }
    __syncthreads();

    unsigned aoff = ((lane&7) + ((lane>>3)&1)*8)*(ST*2) + (lane>>4)*16;
    unsigned boff = ((lane&7) + (lane>>4)*8)*(ST*2) + ((lane>>3)&1)*16;
    unsigned ah_base = sb + AH_OFF + rw*(ST*2) + aoff;
    unsigned al_base = sb + AL_OFF + rw*(ST*2) + aoff;
    unsigned wh1 = sb + WH1_OFF + cb*(ST*2) + boff;
    unsigned wl1 = sb + WL1_OFF + cb*(ST*2) + boff;
    unsigned wh2 = sb + WH2_OFF + cb*(ST*2) + boff;
    unsigned wl2 = sb + WL2_OFF + cb*(ST*2) + boff;

    for (int t=0; t<2; t++){
        int rowbase = blockIdx.x*256 + t*128;

        if (tid < 128){
            int gr = rowbase + tid;
            float s;
            if (pok){
                float sj = g_sjc[gr];
                float v = sF[9];
                #pragma unroll
                for (int k=8;k>=0;k--) v = fmaf(v, sj, sF[k]);
                s = v - fpoly(g_si[gr] + sj) * g_invZ[gr];
            } else {
                s = g_S[gr];
            }
            sS[tid] = s;
        }
        __syncthreads();

        {
            int row = tid >> 2, q = tid & 3, cb2 = q*32;
            float s = sS[row];
            const float4* xr = (const float4*)(x + (size_t)(rowbase+row)*DX + cb2);
            #pragma unroll
            for (int g=0; g<8; g++){
                float4 a = xr[g];
                int col = cb2 + g*4;
                unsigned l0, l1;
                unsigned h0 = pack_split_hi(s*a.x, s*a.y, l0);
                unsigned h1 = pack_split_hi(s*a.z, s*a.w, l1);
                *(unsigned*)(Ah + row*ST + col)     = h0;
                *(unsigned*)(Ah + row*ST + col + 2) = h1;
                *(unsigned*)(Al + row*ST + col)     = l0;
                *(unsigned*)(Al + row*ST + col + 2) = l1;
            }
        }
        __syncthreads();

        float acc[8][4];

        mma_stage_ldm(ah_base, al_base, wh1, wl1, acc);
        __syncthreads();

        {
            int r = lane >> 2, c2 = (lane & 3)*2;
            int R0 = rw + r, R1 = R0 + 8;
            #pragma unroll
            for (int nt=0;nt<8;nt++){
                int n0 = cb + nt*8 + c2;
                float bb0 = __ldg(b1 + n0), bb1 = __ldg(b1 + n0 + 1);
                float h00 = fmaxf(acc[nt][0]+bb0, 0.f);
                float h01 = fmaxf(acc[nt][1]+bb1, 0.f);
                float h10 = fmaxf(acc[nt][2]+bb0, 0.f);
                float h11 = fmaxf(acc[nt][3]+bb1, 0.f);
                unsigned l0, l1;
                unsigned h0 = pack_split_hi(h00, h01, l0);
                unsigned h1 = pack_split_hi(h10, h11, l1);
                *(unsigned*)(Ah + R0*ST + n0) = h0;
                *(unsigned*)(Al + R0*ST + n0) = l0;
                *(unsigned*)(Ah + R1*ST + n0) = h1;
                *(unsigned*)(Al + R1*ST + n0) = l1;
            }
        }
        __syncthreads();

        mma_stage_ldm(ah_base, al_base, wh2, wl2, acc);

        {
            int r = lane >> 2, c2 = (lane & 3)*2;
            int R0 = rw + r, R1 = R0 + 8;
            float sR0 = sS[R0], sR1 = sS[R1];
            const float* x0 = x + (size_t)(rowbase+R0)*DX;
            const float* x1 = x + (size_t)(rowbase+R1)*DX;
            float s0=0.f, q0=0.f, s1=0.f, q1=0.f;
            #pragma unroll
            for (int nt=0;nt<8;nt++){
                int n0 = cb + nt*8 + c2;
                float bb0 = __ldg(b2 + n0), bb1 = __ldg(b2 + n0 + 1);
                float2 xa = *(const float2*)(x0 + n0);
                float2 xb = *(const float2*)(x1 + n0);
                float y00 = acc[nt][0] + bb0 + sR0*xa.x;
                float y01 = acc[nt][1] + bb1 + sR0*xa.y;
                float y10 = acc[nt][2] + bb0 + sR1*xb.x;
                float y11 = acc[nt][3] + bb1 + sR1*xb.y;
                acc[nt][0]=y00; acc[nt][1]=y01; acc[nt][2]=y10; acc[nt][3]=y11;
                s0 += y00+y01; q0 += y00*y00+y01*y01;
                s1 += y10+y11; q1 += y10*y10+y11*y11;
            }
            #pragma unroll
            for (int o=1;o<4;o<<=1){
                s0 += __shfl_xor_sync(0xffffffffu, s0, o);
                q0 += __shfl_xor_sync(0xffffffffu, q0, o);
                s1 += __shfl_xor_sync(0xffffffffu, s1, o);
                q1 += __shfl_xor_sync(0xffffffffu, q1, o);
            }
            if ((lane & 3) == 0){
                sLN[R0*2 + ch] = make_float2(s0, q0);
                sLN[R1*2 + ch] = make_float2(s1, q1);
            }
            __syncthreads();
            float2 o0 = sLN[R0*2 + (ch^1)];
            float2 o1 = sLN[R1*2 + (ch^1)];
            s0 += o0.x; q0 += o0.y;
            s1 += o1.x; q1 += o1.y;
            float mu0  = s0 * (1.0f/128.0f);
            float inv0 = rsqrtf(q0*(1.0f/128.0f) - mu0*mu0 + 1e-6f);
            float mu1  = s1 * (1.0f/128.0f);
            float inv1 = rsqrtf(q1*(1.0f/128.0f) - mu1*mu1 + 1e-6f);
            float* p0 = out + (size_t)(rowbase+R0)*DX;
            float* p1 = out + (size_t)(rowbase+R1)*DX;
            #pragma unroll
            for (int nt=0;nt<8;nt++){
                int n0 = cb + nt*8 + c2;
                float2 gg = *(const float2*)(lng + n0);
                float2 be = *(const float2*)(lnb + n0);
                float2 v0, v1;
                v0.x = (acc[nt][0]-mu0)*inv0*gg.x + be.x;
                v0.y = (acc[nt][1]-mu0)*inv0*gg.y + be.y;
                v1.x = (acc[nt][2]-mu1)*inv1*gg.x + be.x;
                v1.y = (acc[nt][3]-mu1)*inv1*gg.y + be.y;
                *(float2*)(p0 + n0) = v0;
                *(float2*)(p1 + n0) = v1;
            }
        }
        __syncthreads();
    }
}

// ---------------- launch ----------------
extern "C" void kernel_launch(void* const* d_in, const int* in_sizes, int n_in,
                              void* d_out, int out_size)
{
    const float* x     = (const float*)d_in[0];
    const float* W1    = (const float*)d_in[2];
    const float* wt_w  = (const float*)d_in[4];
    const float* Wsa1  = (const float*)d_in[6];
    const float* Wsa2  = (const float*)d_in[7];
    const float* wsatw = (const float*)d_in[8];
    const float* wsatb = (const float*)d_in[9];
    const float* bsa1  = (const float*)d_in[10];
    const float* pw1   = (const float*)d_in[11];
    const float* pb1   = (const float*)d_in[12];
    const float* pw2   = (const float*)d_in[13];
    const float* pb2   = (const float*)d_in[14];
    const float* lng   = (const float*)d_in[15];
    const float* lnb   = (const float*)d_in[16];
    float* out = (float*)d_out;

    kmega<<<GRIDN,512>>>(x, W1, wt_w, Wsa1, Wsa2, wsatw, wsatb, bsa1, pw1, pw2);

    cudaFuncSetAttribute(kffn, cudaFuncAttributeMaxDynamicSharedMemorySize, KFFN_SMEM);
    kffn<<<GRIDN,512,KFFN_SMEM>>>(x, pb1, pb2, lng, lnb, out);
}

// round 16
// speedup vs baseline: 1.0029x; 1.0029x over previous
#include <cuda_runtime.h>
#include <cuda_bf16.h>
#include <cstring>

typedef unsigned long long ull;

#define BB 8
#define LL 4096
#define DX 128
#define BL (BB*LL)
#define GRIDN 128
#define SLICES 16
#define SLEN (LL/SLICES)
#define ST 136            // padded bf16 row stride (272B; conflict-free for ldmatrix)

// ---------------- scratch ----------------
__device__ __align__(16) float g_v1[DX], g_u1[DX], g_u2[DX];
__device__ float g_cconst;
__device__ float g_logits[BL], g_d1[BL], g_d2[BL];
__device__ float g_si[BL], g_sjc[BL];
__device__ float g_invZ[BL], g_S[BL];
__device__ float g_Mpart[GRIDN*10], g_Fpart[GRIDN*10];
__device__ float g_psum[GRIDN];
__device__ unsigned g_lmax[BB];
__device__ unsigned g_msi, g_msjc;
__device__ ull g_barcnt = 0;

// pre-transposed bf16-split weight images: [n][k] row-major, stride ST
__device__ __align__(16) __nv_bfloat16 g_w1hi[128*ST], g_w1lo[128*ST];
__device__ __align__(16) __nv_bfloat16 g_w2hi[128*ST], g_w2lo[128*ST];

// ---------------- exp(sigmoid(t)) Taylor deg-9, valid |t|<=1 ----------------
#define P0f  1.64872127f
#define P1f  0.412180318f
#define P2f  0.0515225397f
#define P3f (-0.03005490f)
#define P4f (-0.00831874f)
#define P5f  0.00237489f
#define P6f  0.00112763f
#define P7f (-1.56355e-4f)
#define P8f (-1.38606e-4f)
#define P9f  5.4551e-6f

__constant__ float c_P[10] = {P0f,P1f,P2f,P3f,P4f,P5f,P6f,P7f,P8f,P9f};
__constant__ float c_BIN[10][10] = {
    {1,0,0,0,0,0,0,0,0,0},
    {1,1,0,0,0,0,0,0,0,0},
    {1,2,1,0,0,0,0,0,0,0},
    {1,3,3,1,0,0,0,0,0,0},
    {1,4,6,4,1,0,0,0,0,0},
    {1,5,10,10,5,1,0,0,0,0},
    {1,6,15,20,15,6,1,0,0,0},
    {1,7,21,35,35,21,7,1,0,0},
    {1,8,28,56,70,56,28,8,1,0},
    {1,9,36,84,126,126,84,36,9,1},
};

__device__ __forceinline__ float fpoly(float t){
    float r = P9f;
    r = fmaf(r,t,P8f); r = fmaf(r,t,P7f); r = fmaf(r,t,P6f);
    r = fmaf(r,t,P5f); r = fmaf(r,t,P4f); r = fmaf(r,t,P3f);
    r = fmaf(r,t,P2f); r = fmaf(r,t,P1f); r = fmaf(r,t,P0f);
    return r;
}

__device__ __forceinline__ float ex2a(float x){ float r; asm("ex2.approx.ftz.f32 %0,%1;":"=f"(r):"f"(x)); return r; }
__device__ __forceinline__ float rcpa(float x){ float r; asm("rcp.approx.ftz.f32 %0,%1;":"=f"(r):"f"(x)); return r; }
__device__ __forceinline__ float fsig(float t){
    const float L2E = 1.44269504088896f;
    float e = ex2a(t * -L2E);
    float s = rcpa(1.0f + e);
    return ex2a(s * L2E);
}

__device__ __forceinline__ bool poly_ok(){
    return (__uint_as_float(g_msi) + __uint_as_float(g_msjc)) <= 1.0f;
}

__device__ __forceinline__ unsigned fkey(float f){
    unsigned u = __float_as_uint(f);
    return (u & 0x80000000u) ? ~u : (u | 0x80000000u);
}
__device__ __forceinline__ float funkey(unsigned k){
    unsigned u = (k & 0x80000000u) ? (k ^ 0x80000000u) : ~k;
    return __uint_as_float(u);
}

__device__ __forceinline__ float wradd(float v){
    #pragma unroll
    for (int o=16;o;o>>=1) v += __shfl_xor_sync(0xffffffffu, v, o);
    return v;
}

// ---------------- bf16 helpers ----------------
__device__ __forceinline__ unsigned pack_split_hi(float a, float b, unsigned &plo){
    __nv_bfloat16 ha = __float2bfloat16(a);
    __nv_bfloat16 la = __float2bfloat16(a - __bfloat162float(ha));
    __nv_bfloat16 hb = __float2bfloat16(b);
    __nv_bfloat16 lb = __float2bfloat16(b - __bfloat162float(hb));
    __nv_bfloat162 th; th.x = ha; th.y = hb;
    __nv_bfloat162 tl; tl.x = la; tl.y = lb;
    unsigned uh, ul;
    memcpy(&uh, &th, 4); memcpy(&ul, &tl, 4);
    plo = ul;
    return uh;
}

__device__ __forceinline__ void mma16816(float c[4],
        unsigned a0, unsigned a1, unsigned a2, unsigned a3,
        unsigned b0, unsigned b1)
{
    asm("mma.sync.aligned.m16n8k16.row.col.f32.bf16.bf16.f32 "
        "{%0,%1,%2,%3}, {%4,%5,%6,%7}, {%8,%9}, {%0,%1,%2,%3};"
        : "+f"(c[0]), "+f"(c[1]), "+f"(c[2]), "+f"(c[3])
        : "r"(a0), "r"(a1), "r"(a2), "r"(a3), "r"(b0), "r"(b1));
}

__device__ __forceinline__ void ldm_x4(unsigned r[4], unsigned addr){
    asm volatile("ldmatrix.sync.aligned.m8n8.x4.shared.b16 {%0,%1,%2,%3}, [%4];"
        : "=r"(r[0]), "=r"(r[1]), "=r"(r[2]), "=r"(r[3]) : "r"(addr));
}

// ---------------- grid barrier ----------------
__device__ __forceinline__ void gsync(){
    __syncthreads();
    if (threadIdx.x == 0){
        __threadfence();
        ull t = atomicAdd(&g_barcnt, 1ull);
        ull target = (t/GRIDN + 1ull) * (ull)GRIDN;
        while (*((volatile ull*)&g_barcnt) < target) __nanosleep(64);
        __threadfence();
    }
    __syncthreads();
}

// ================= MEGA KERNEL =================
__global__ void __launch_bounds__(512) kmega(
        const float* __restrict__ x,
        const float* __restrict__ W1,  const float* __restrict__ wt_w,
        const float* __restrict__ Wsa1,const float* __restrict__ Wsa2,
        const float* __restrict__ wsat_w, const float* __restrict__ wsat_b,
        const float* __restrict__ bsa1,
        const float* __restrict__ pw1, const float* __restrict__ pw2)
{
    __shared__ __align__(16) float sbuf[8192];
    __shared__ float sred[16];
    __shared__ float smom[8][10];
    __shared__ float sE[10];

    int tid  = threadIdx.x;
    int lane = tid & 31, wid = tid >> 5;
    int bk = blockIdx.x;
    int b  = bk >> 4;
    int s  = bk & 15;

    // ---------- phase 0: prep + weight image build ----------
    if (bk < 3){
        float* vec = sbuf;
        float* sp  = sbuf + 128;
        if (tid < DX) vec[tid] = (bk==0) ? wt_w[tid] : wsat_w[tid];
        __syncthreads();
        const float* W = (bk==0)?W1:(bk==1)?Wsa1:Wsa2;
        int d = tid & 127, p = tid >> 7;
        float a = 0.f;
        #pragma unroll 8
        for (int e=p*32; e<p*32+32; e++) a = fmaf(W[d*DX+e], vec[e], a);
        sp[p*DX + d] = a;
        __syncthreads();
        if (tid < DX){
            float t = (sp[tid]+sp[DX+tid]) + (sp[2*DX+tid]+sp[3*DX+tid]);
            float* dst = (bk==0)?g_v1:(bk==1)?g_u1:g_u2;
            dst[tid] = t;
        }
    } else if (bk == 3){
        if (tid < DX) sbuf[tid] = bsa1[tid]*wsat_w[tid];
        __syncthreads();
        for (int o=64;o;o>>=1){ if(tid<o) sbuf[tid]+=sbuf[tid+o]; __syncthreads(); }
        if (tid==0){ g_cconst = sbuf[0] + wsat_b[0]; g_msi=0u; g_msjc=0u; }
        if (tid < BB) g_lmax[tid] = 0u;
    } else if (bk == 4 || bk == 5){
        const float* W = (bk==4) ? pw1 : pw2;
        __nv_bfloat16* ih = (bk==4) ? g_w1hi : g_w2hi;
        __nv_bfloat16* il = (bk==4) ? g_w1lo : g_w2lo;
        for (int idx=tid; idx<16384; idx+=512){
            int k = idx & 127, n = idx >> 7;
            float v = W[k*DX + n];
            __nv_bfloat16 h = __float2bfloat16(v);
            __nv_bfloat16 l = __float2bfloat16(v - __bfloat162float(h));
            ih[n*ST + k] = h;
            il[n*ST + k] = l;
        }
    }
    gsync();

    // ---------- phase 1: per-row dots + block logit max ----------
    {
        float4 av = ((const float4*)g_v1)[lane];
        float4 bv = ((const float4*)g_u1)[lane];
        float4 cv = ((const float4*)g_u2)[lane];
        int rowbase = bk*SLEN + wid*16;
        float lmax = -1e30f;
        #pragma unroll 2
        for (int r=0;r<16;r++){
            int row = rowbase + r;
            float4 xv = ((const float4*)x)[row*32 + lane];
            float s0 = xv.x*av.x + xv.y*av.y + xv.z*av.z + xv.w*av.w;
            float s1 = xv.x*bv.x + xv.y*bv.y + xv.z*bv.z + xv.w*bv.w;
            float s2 = xv.x*cv.x + xv.y*cv.y + xv.z*cv.z + xv.w*cv.w;
            #pragma unroll
            for (int o=16;o;o>>=1){
                s0 += __shfl_down_sync(0xffffffffu, s0, o);
                s1 += __shfl_down_sync(0xffffffffu, s1, o);
                s2 += __shfl_down_sync(0xffffffffu, s2, o);
            }
            if (lane==0){
                g_logits[row]=s0; g_d1[row]=s1; g_d2[row]=s2;
                lmax = fmaxf(lmax, s0);
            }
        }
        if (lane==0) sred[wid] = lmax;
        __syncthreads();
        if (tid==0){
            float m = sred[0];
            #pragma unroll
            for (int w=1;w<16;w++) m = fmaxf(m, sred[w]);
            atomicMax(&g_lmax[b], fkey(m));
        }
    }
    gsync();

    // ---------- phase 2: partial softmax sums ----------
    {
        float m = funkey(g_lmax[b]);
        if (tid < SLEN){
            float v = __expf(g_logits[b*LL + s*SLEN + tid] - m);
            v = wradd(v);
            if (lane==0) sred[wid] = v;
        }
        __syncthreads();
        if (tid==0){
            float t = 0.f;
            #pragma unroll
            for (int w=0;w<8;w++) t += sred[w];
            g_psum[bk] = t;
        }
    }
    gsync();

    // ---------- phase 3: si/sjc + ranges + partial sjc-moments ----------
    {
        float m = funkey(g_lmax[b]);
        float t = 0.f;
        #pragma unroll
        for (int k=0;k<SLICES;k++) t += g_psum[b*SLICES+k];
        float inv = 1.0f/t;
        float cc = g_cconst;
        if (tid < SLEN){
            int idx = b*LL + s*SLEN + tid;
            float p = __expf(g_logits[idx]-m)*inv;
            float si  = p*g_d1[idx];
            float sjc = fmaf(p, g_d2[idx], cc);
            g_si[idx]=si; g_sjc[idx]=sjc;
            float rs = fabsf(si), rj = fabsf(sjc);
            #pragma unroll
            for (int o=16;o;o>>=1){
                rs = fmaxf(rs, __shfl_xor_sync(0xffffffffu, rs, o));
                rj = fmaxf(rj, __shfl_xor_sync(0xffffffffu, rj, o));
            }
            if (lane==0){
                atomicMax(&g_msi,  __float_as_uint(rs));
                atomicMax(&g_msjc, __float_as_uint(rj));
            }
            float pw = 1.f;
            #pragma unroll
            for (int k=0;k<10;k++){
                float v = wradd(pw);
                if (lane==0) smom[wid][k]=v;
                pw *= sjc;
            }
        }
        __syncthreads();
        if (tid < 10){
            float acc = 0.f;
            #pragma unroll
            for (int w=0;w<8;w++) acc += smom[w][tid];
            g_Mpart[bk*10 + tid] = acc;
        }
    }
    gsync();

    bool pok = poly_ok();

    if (pok){
        // ---------- phase 4: invZ + partial invZ-weighted si-moments ----------
        if (tid < 10){
            float M[10];
            #pragma unroll
            for (int mi=0;mi<10;mi++){
                float acc = 0.f;
                #pragma unroll
                for (int ss=0;ss<SLICES;ss++) acc += g_Mpart[(b*SLICES+ss)*10 + mi];
                M[mi] = acc;
            }
            float e = 0.f;
            for (int mi=0; tid+mi<10; mi++)
                e = fmaf(c_P[tid+mi]*c_BIN[tid+mi][tid], M[mi], e);
            sE[tid] = e;
        }
        __syncthreads();
        if (tid < SLEN){
            int idx = b*LL + s*SLEN + tid;
            float si = g_si[idx], sjc = g_sjc[idx];
            float z = sE[9];
            #pragma unroll
            for (int k=8;k>=0;k--) z = fmaf(z, si, sE[k]);
            z -= fpoly(si + sjc);
            float w = 1.0f / z;
            g_invZ[idx] = w;
            float pw = w;
            #pragma unroll
            for (int k=0;k<10;k++){
                float v = wradd(pw);
                if (lane==0) smom[wid][k]=v;
                pw *= si;
            }
        }
        __syncthreads();
        if (tid < 10){
            float acc = 0.f;
            #pragma unroll
            for (int w=0;w<8;w++) acc += smom[w][tid];
            g_Fpart[bk*10 + tid] = acc;
        }
    } else {
        // ---------- fallback: full O(L^2) row/col sums ----------
        {
            for (int k=tid;k<LL;k+=512) sbuf[k] = g_sjc[b*LL+k];
            __syncthreads();
            int row = b*LL + s*SLEN + (tid>>1);
            int half = tid & 1;
            float si = g_si[row];
            float a = 0.f;
            for (int j=half*2048; j<half*2048+2048; j++) a += fsig(si + sbuf[j]);
            a += __shfl_xor_sync(0xffffffffu, a, 1);
            if (half==0){
                float Z = a - fsig(si + g_sjc[row]);
                g_invZ[row] = 1.0f / Z;
            }
        }
        gsync();
        {
            float* s_si = sbuf;
            float* s_wz = sbuf + 4096;
            for (int k=tid;k<LL;k+=512){ s_si[k]=g_si[b*LL+k]; s_wz[k]=g_invZ[b*LL+k]; }
            __syncthreads();
            int col = b*LL + s*SLEN + (tid>>1);
            int half = tid & 1;
            float sj = g_sjc[col];
            float a = 0.f;
            for (int i=half*2048; i<half*2048+2048; i++)
                a = fmaf(fsig(sj + s_si[i]), s_wz[i], a);
            a += __shfl_xor_sync(0xffffffffu, a, 1);
            if (half==0)
                g_S[col] = a - fsig(g_si[col] + sj) * g_invZ[col];
        }
    }
}

// ================= kffn: persistent, 512 threads, warp = 16 rows x 64 cols =================
#define IMGB (128*ST*2)
#define WH1_OFF 4096u
#define WL1_OFF (4096u + IMGB)
#define WH2_OFF (4096u + 2*IMGB)
#define WL2_OFF (4096u + 3*IMGB)
#define AH_OFF  (4096u + 4*IMGB)
#define AL_OFF  (4096u + 5*IMGB)
#define KFFN_SMEM (4096 + 6*IMGB)

// B fragments for all 4 ntp loaded up-front; combo-outer ordering gives
// dependency distance of 8 independent MMAs per accumulator reuse.
__device__ __forceinline__ void mma_stage_ldm(
        unsigned ah_base, unsigned al_base,
        unsigned wh_base, unsigned wl_base,
        float acc[8][4])
{
    #pragma unroll
    for (int nt=0;nt<8;nt++){
        acc[nt][0]=0.f; acc[nt][1]=0.f; acc[nt][2]=0.f; acc[nt][3]=0.f;
    }
    #pragma unroll
    for (int k=0;k<8;k++){
        unsigned kb = k*32;
        unsigned ah[4], al[4];
        ldm_x4(ah, ah_base + kb);
        ldm_x4(al, al_base + kb);
        unsigned bh[4][4], bl[4][4];
        #pragma unroll
        for (int ntp=0;ntp<4;ntp++){
            unsigned pb = ntp*16*(ST*2) + kb;
            ldm_x4(bh[ntp], wh_base + pb);
            ldm_x4(bl[ntp], wl_base + pb);
        }
        // combo 1: Ahi * Bhi
        #pragma unroll
        for (int ntp=0;ntp<4;ntp++){
            mma16816(acc[2*ntp],   ah[0],ah[1],ah[2],ah[3], bh[ntp][0],bh[ntp][1]);
            mma16816(acc[2*ntp+1], ah[0],ah[1],ah[2],ah[3], bh[ntp][2],bh[ntp][3]);
        }
        // combo 2: Ahi * Blo
        #pragma unroll
        for (int ntp=0;ntp<4;ntp++){
            mma16816(acc[2*ntp],   ah[0],ah[1],ah[2],ah[3], bl[ntp][0],bl[ntp][1]);
            mma16816(acc[2*ntp+1], ah[0],ah[1],ah[2],ah[3], bl[ntp][2],bl[ntp][3]);
        }
        // combo 3: Alo * Bhi
        #pragma unroll
        for (int ntp=0;ntp<4;ntp++){
            mma16816(acc[2*ntp],   al[0],al[1],al[2],al[3], bh[ntp][0],bh[ntp][1]);
            mma16816(acc[2*ntp+1], al[0],al[1],al[2],al[3], bh[ntp][2],bh[ntp][3]);
        }
    }
}

__global__ void __launch_bounds__(512) kffn(const float* __restrict__ x,
        const float* __restrict__ b1, const float* __restrict__ b2,
        const float* __restrict__ lng, const float* __restrict__ lnb,
        float* __restrict__ out)
{
    extern __shared__ __align__(16) char smc[];
    unsigned sb;
    asm("{ .reg .u64 t; cvta.to.shared.u64 t, %1; cvt.u32.u64 %0, t; }" : "=r"(sb) : "l"(smc));

    float*  sS  = (float*)smc;            // 128 floats
    float*  sF  = (float*)(smc + 512);    // 10 floats
    float2* sLN = (float2*)(smc + 1024);  // 128 rows x 2 halves (2KB)
    __nv_bfloat16* Ah = (__nv_bfloat16*)(smc + AH_OFF);
    __nv_bfloat16* Al = (__nv_bfloat16*)(smc + AL_OFF);

    int tid = threadIdx.x;
    int lane = tid & 31, w = tid >> 5;
    int rw = (w & 7) * 16;
    int ch = w >> 3;
    int cb = ch * 64;
    int b = (blockIdx.x * 256) >> 12;
    bool pok = poly_ok();

    if (pok && tid < 10){
        float M[10];
        #pragma unroll
        for (int mi=0;mi<10;mi++){
            float acc = 0.f;
            #pragma unroll
            for (int ss=0;ss<SLICES;ss++) acc += g_Fpart[(b*SLICES+ss)*10 + mi];
            M[mi] = acc;
        }
        float e = 0.f;
        for (int mi=0; tid+mi<10; mi++)
            e = fmaf(c_P[tid+mi]*c_BIN[tid+mi][tid], M[mi], e);
        sF[tid] = e;
    }
    {
        const float4* s1 = (const float4*)g_w1hi;
        const float4* s2 = (const float4*)g_w1lo;
        const float4* s3 = (const float4*)g_w2hi;
        const float4* s4 = (const float4*)g_w2lo;
        float4* d1 = (float4*)(smc + WH1_OFF);
        float4* d2 = (float4*)(smc + WL1_OFF);
        float4* d3 = (float4*)(smc + WH2_OFF);
        float4* d4 = (float4*)(smc + WL2_OFF);
        for (int k=tid; k<IMGB/16; k+=512){ d1[k]=s1[k]; d2[k]=s2[k]; d3[k]=s3[k]; d4[k]=s4[k]; }
    }
    __syncthreads();

    unsigned aoff = ((lane&7) + ((lane>>3)&1)*8)*(ST*2) + (lane>>4)*16;
    unsigned boff = ((lane&7) + (lane>>4)*8)*(ST*2) + ((lane>>3)&1)*16;
    unsigned ah_base = sb + AH_OFF + rw*(ST*2) + aoff;
    unsigned al_base = sb + AL_OFF + rw*(ST*2) + aoff;
    unsigned wh1 = sb + WH1_OFF + cb*(ST*2) + boff;
    unsigned wl1 = sb + WL1_OFF + cb*(ST*2) + boff;
    unsigned wh2 = sb + WH2_OFF + cb*(ST*2) + boff;
    unsigned wl2 = sb + WL2_OFF + cb*(ST*2) + boff;

    for (int t=0; t<2; t++){
        int rowbase = blockIdx.x*256 + t*128;

        if (tid < 128){
            int gr = rowbase + tid;
            float s;
            if (pok){
                float sj = g_sjc[gr];
                float v = sF[9];
                #pragma unroll
                for (int k=8;k>=0;k--) v = fmaf(v, sj, sF[k]);
                s = v - fpoly(g_si[gr] + sj) * g_invZ[gr];
            } else {
                s = g_S[gr];
            }
            sS[tid] = s;
        }
        __syncthreads();

        {
            int row = tid >> 2, q = tid & 3, cb2 = q*32;
            float s = sS[row];
            const float4* xr = (const float4*)(x + (size_t)(rowbase+row)*DX + cb2);
            #pragma unroll
            for (int g=0; g<8; g++){
                float4 a = xr[g];
                int col = cb2 + g*4;
                unsigned l0, l1;
                unsigned h0 = pack_split_hi(s*a.x, s*a.y, l0);
                unsigned h1 = pack_split_hi(s*a.z, s*a.w, l1);
                *(unsigned*)(Ah + row*ST + col)     = h0;
                *(unsigned*)(Ah + row*ST + col + 2) = h1;
                *(unsigned*)(Al + row*ST + col)     = l0;
                *(unsigned*)(Al + row*ST + col + 2) = l1;
            }
        }
        __syncthreads();

        float acc[8][4];

        mma_stage_ldm(ah_base, al_base, wh1, wl1, acc);
        __syncthreads();

        {
            int r = lane >> 2, c2 = (lane & 3)*2;
            int R0 = rw + r, R1 = R0 + 8;
            #pragma unroll
            for (int nt=0;nt<8;nt++){
                int n0 = cb + nt*8 + c2;
                float bb0 = __ldg(b1 + n0), bb1 = __ldg(b1 + n0 + 1);
                float h00 = fmaxf(acc[nt][0]+bb0, 0.f);
                float h01 = fmaxf(acc[nt][1]+bb1, 0.f);
                float h10 = fmaxf(acc[nt][2]+bb0, 0.f);
                float h11 = fmaxf(acc[nt][3]+bb1, 0.f);
                unsigned l0, l1;
                unsigned h0 = pack_split_hi(h00, h01, l0);
                unsigned h1 = pack_split_hi(h10, h11, l1);
                *(unsigned*)(Ah + R0*ST + n0) = h0;
                *(unsigned*)(Al + R0*ST + n0) = l0;
                *(unsigned*)(Ah + R1*ST + n0) = h1;
                *(unsigned*)(Al + R1*ST + n0) = l1;
            }
        }
        __syncthreads();

        mma_stage_ldm(ah_base, al_base, wh2, wl2, acc);

        {
            int r = lane >> 2, c2 = (lane & 3)*2;
            int R0 = rw + r, R1 = R0 + 8;
            float sR0 = sS[R0], sR1 = sS[R1];
            const float* x0 = x + (size_t)(rowbase+R0)*DX;
            const float* x1 = x + (size_t)(rowbase+R1)*DX;
            float s0=0.f, q0=0.f, s1=0.f, q1=0.f;
            #pragma unroll
            for (int nt=0;nt<8;nt++){
                int n0 = cb + nt*8 + c2;
                float bb0 = __ldg(b2 + n0), bb1 = __ldg(b2 + n0 + 1);
                float2 xa = *(const float2*)(x0 + n0);
                float2 xb = *(const float2*)(x1 + n0);
                float y00 = acc[nt][0] + bb0 + sR0*xa.x;
                float y01 = acc[nt][1] + bb1 + sR0*xa.y;
                float y10 = acc[nt][2] + bb0 + sR1*xb.x;
                float y11 = acc[nt][3] + bb1 + sR1*xb.y;
                acc[nt][0]=y00; acc[nt][1]=y01; acc[nt][2]=y10; acc[nt][3]=y11;
                s0 += y00+y01; q0 += y00*y00+y01*y01;
                s1 += y10+y11; q1 += y10*y10+y11*y11;
            }
            #pragma unroll
            for (int o=1;o<4;o<<=1){
                s0 += __shfl_xor_sync(0xffffffffu, s0, o);
                q0 += __shfl_xor_sync(0xffffffffu, q0, o);
                s1 += __shfl_xor_sync(0xffffffffu, s1, o);
                q1 += __shfl_xor_sync(0xffffffffu, q1, o);
            }
            if ((lane & 3) == 0){
                sLN[R0*2 + ch] = make_float2(s0, q0);
                sLN[R1*2 + ch] = make_float2(s1, q1);
            }
            __syncthreads();
            float2 o0 = sLN[R0*2 + (ch^1)];
            float2 o1 = sLN[R1*2 + (ch^1)];
            s0 += o0.x; q0 += o0.y;
            s1 += o1.x; q1 += o1.y;
            float mu0  = s0 * (1.0f/128.0f);
            float inv0 = rsqrtf(q0*(1.0f/128.0f) - mu0*mu0 + 1e-6f);
            float mu1  = s1 * (1.0f/128.0f);
            float inv1 = rsqrtf(q1*(1.0f/128.0f) - mu1*mu1 + 1e-6f);
            float* p0 = out + (size_t)(rowbase+R0)*DX;
            float* p1 = out + (size_t)(rowbase+R1)*DX;
            #pragma unroll
            for (int nt=0;nt<8;nt++){
                int n0 = cb + nt*8 + c2;
                float2 gg = *(const float2*)(lng + n0);
                float2 be = *(const float2*)(lnb + n0);
                float2 v0, v1;
                v0.x = (acc[nt][0]-mu0)*inv0*gg.x + be.x;
                v0.y = (acc[nt][1]-mu0)*inv0*gg.y + be.y;
                v1.x = (acc[nt][2]-mu1)*inv1*gg.x + be.x;
                v1.y = (acc[nt][3]-mu1)*inv1*gg.y + be.y;
                *(float2*)(p0 + n0) = v0;
                *(float2*)(p1 + n0) = v1;
            }
        }
        __syncthreads();
    }
}

// ---------------- launch ----------------
extern "C" void kernel_launch(void* const* d_in, const int* in_sizes, int n_in,
                              void* d_out, int out_size)
{
    const float* x     = (const float*)d_in[0];
    const float* W1    = (const float*)d_in[2];
    const float* wt_w  = (const float*)d_in[4];
    const float* Wsa1  = (const float*)d_in[6];
    const float* Wsa2  = (const float*)d_in[7];
    const float* wsatw = (const float*)d_in[8];
    const float* wsatb = (const float*)d_in[9];
    const float* bsa1  = (const float*)d_in[10];
    const float* pw1   = (const float*)d_in[11];
    const float* pb1   = (const float*)d_in[12];
    const float* pw2   = (const float*)d_in[13];
    const float* pb2   = (const float*)d_in[14];
    const float* lng   = (const float*)d_in[15];
    const float* lnb   = (const float*)d_in[16];
    float* out = (float*)d_out;

    kmega<<<GRIDN,512>>>(x, W1, wt_w, Wsa1, Wsa2, wsatw, wsatb, bsa1, pw1, pw2);

    cudaFuncSetAttribute(kffn, cudaFuncAttributeMaxDynamicSharedMemorySize, KFFN_SMEM);
    kffn<<<GRIDN,512,KFFN_SMEM>>>(x, pb1, pb2, lng, lnb, out);
}

// round 17
// speedup vs baseline: 1.0142x; 1.0113x over previous
#include <cuda_runtime.h>
#include <cuda_bf16.h>
#include <cstring>

typedef unsigned long long ull;

#define BB 8
#define LL 4096
#define DX 128
#define BL (BB*LL)
#define GRIDN 128
#define SLICES 16
#define SLEN (LL/SLICES)
#define ST 136

// ---------------- scratch ----------------
__device__ __align__(16) float g_v1[DX], g_u1[DX], g_u2[DX];
__device__ float g_cconst;
__device__ float g_logits[BL], g_d1[BL], g_d2[BL];
__device__ float g_si[BL], g_sjc[BL];
__device__ float g_invZ[BL], g_S[BL];
__device__ float g_Mpart[GRIDN*10], g_Fpart[GRIDN*10];
__device__ float g_psum[GRIDN];
__device__ unsigned g_lmax[BB];
__device__ unsigned g_msi, g_msjc;
__device__ ull g_barcnt = 0;

__device__ __align__(16) __nv_bfloat16 g_w1hi[128*ST], g_w1lo[128*ST];
__device__ __align__(16) __nv_bfloat16 g_w2hi[128*ST], g_w2lo[128*ST];

// ---------------- exp(sigmoid(t)) Taylor deg-9, valid |t|<=1 ----------------
#define P0f  1.64872127f
#define P1f  0.412180318f
#define P2f  0.0515225397f
#define P3f (-0.03005490f)
#define P4f (-0.00831874f)
#define P5f  0.00237489f
#define P6f  0.00112763f
#define P7f (-1.56355e-4f)
#define P8f (-1.38606e-4f)
#define P9f  5.4551e-6f

__constant__ float c_P[10] = {P0f,P1f,P2f,P3f,P4f,P5f,P6f,P7f,P8f,P9f};
__constant__ float c_BIN[10][10] = {
    {1,0,0,0,0,0,0,0,0,0},
    {1,1,0,0,0,0,0,0,0,0},
    {1,2,1,0,0,0,0,0,0,0},
    {1,3,3,1,0,0,0,0,0,0},
    {1,4,6,4,1,0,0,0,0,0},
    {1,5,10,10,5,1,0,0,0,0},
    {1,6,15,20,15,6,1,0,0,0},
    {1,7,21,35,35,21,7,1,0,0},
    {1,8,28,56,70,56,28,8,1,0},
    {1,9,36,84,126,126,84,36,9,1},
};

__device__ __forceinline__ float fpoly(float t){
    float r = P9f;
    r = fmaf(r,t,P8f); r = fmaf(r,t,P7f); r = fmaf(r,t,P6f);
    r = fmaf(r,t,P5f); r = fmaf(r,t,P4f); r = fmaf(r,t,P3f);
    r = fmaf(r,t,P2f); r = fmaf(r,t,P1f); r = fmaf(r,t,P0f);
    return r;
}

__device__ __forceinline__ float ex2a(float x){ float r; asm("ex2.approx.ftz.f32 %0,%1;":"=f"(r):"f"(x)); return r; }
__device__ __forceinline__ float rcpa(float x){ float r; asm("rcp.approx.ftz.f32 %0,%1;":"=f"(r):"f"(x)); return r; }
__device__ __forceinline__ float fsig(float t){
    const float L2E = 1.44269504088896f;
    float e = ex2a(t * -L2E);
    float s = rcpa(1.0f + e);
    return ex2a(s * L2E);
}

__device__ __forceinline__ bool poly_ok(){
    return (__uint_as_float(g_msi) + __uint_as_float(g_msjc)) <= 1.0f;
}

__device__ __forceinline__ unsigned fkey(float f){
    unsigned u = __float_as_uint(f);
    return (u & 0x80000000u) ? ~u : (u | 0x80000000u);
}
__device__ __forceinline__ float funkey(unsigned k){
    unsigned u = (k & 0x80000000u) ? (k ^ 0x80000000u) : ~k;
    return __uint_as_float(u);
}

__device__ __forceinline__ float wradd(float v){
    #pragma unroll
    for (int o=16;o;o>>=1) v += __shfl_xor_sync(0xffffffffu, v, o);
    return v;
}

// ---------------- bf16 helpers ----------------
__device__ __forceinline__ unsigned pack_split_hi(float a, float b, unsigned &plo){
    __nv_bfloat16 ha = __float2bfloat16(a);
    __nv_bfloat16 la = __float2bfloat16(a - __bfloat162float(ha));
    __nv_bfloat16 hb = __float2bfloat16(b);
    __nv_bfloat16 lb = __float2bfloat16(b - __bfloat162float(hb));
    __nv_bfloat162 th; th.x = ha; th.y = hb;
    __nv_bfloat162 tl; tl.x = la; tl.y = lb;
    unsigned uh, ul;
    memcpy(&uh, &th, 4); memcpy(&ul, &tl, 4);
    plo = ul;
    return uh;
}

__device__ __forceinline__ void mma16816(float c[4],
        unsigned a0, unsigned a1, unsigned a2, unsigned a3,
        unsigned b0, unsigned b1)
{
    asm("mma.sync.aligned.m16n8k16.row.col.f32.bf16.bf16.f32 "
        "{%0,%1,%2,%3}, {%4,%5,%6,%7}, {%8,%9}, {%0,%1,%2,%3};"
        : "+f"(c[0]), "+f"(c[1]), "+f"(c[2]), "+f"(c[3])
        : "r"(a0), "r"(a1), "r"(a2), "r"(a3), "r"(b0), "r"(b1));
}

__device__ __forceinline__ void ldm_x4(unsigned r[4], unsigned addr){
    asm volatile("ldmatrix.sync.aligned.m8n8.x4.shared.b16 {%0,%1,%2,%3}, [%4];"
        : "=r"(r[0]), "=r"(r[1]), "=r"(r[2]), "=r"(r[3]) : "r"(addr));
}

// ---------------- grid barrier ----------------
__device__ __forceinline__ void gsync(){
    __syncthreads();
    if (threadIdx.x == 0){
        __threadfence();
        ull t = atomicAdd(&g_barcnt, 1ull);
        ull target = (t/GRIDN + 1ull) * (ull)GRIDN;
        while (*((volatile ull*)&g_barcnt) < target) __nanosleep(64);
        __threadfence();
    }
    __syncthreads();
}

// ---------------- smem layout (dynamic, 213KB) ----------------
#define IMGB (128*ST*2)
#define WH1_OFF 4096u
#define WL1_OFF (4096u + IMGB)
#define WH2_OFF (4096u + 2*IMGB)
#define WL2_OFF (4096u + 3*IMGB)
#define AH_OFF  (4096u + 4*IMGB)
#define AL_OFF  (4096u + 5*IMGB)
#define KSMEM   (4096 + 6*IMGB)

__device__ __forceinline__ void mma_stage_ldm(
        unsigned ah_base, unsigned al_base,
        unsigned wh_base, unsigned wl_base,
        float acc[8][4])
{
    #pragma unroll
    for (int nt=0;nt<8;nt++){
        acc[nt][0]=0.f; acc[nt][1]=0.f; acc[nt][2]=0.f; acc[nt][3]=0.f;
    }
    #pragma unroll
    for (int k=0;k<8;k++){
        unsigned kb = k*32;
        unsigned ah[4], al[4];
        ldm_x4(ah, ah_base + kb);
        ldm_x4(al, al_base + kb);
        unsigned bh[4][4], bl[4][4];
        #pragma unroll
        for (int ntp=0;ntp<4;ntp++){
            unsigned pb = ntp*16*(ST*2) + kb;
            ldm_x4(bh[ntp], wh_base + pb);
            ldm_x4(bl[ntp], wl_base + pb);
        }
        #pragma unroll
        for (int ntp=0;ntp<4;ntp++){
            mma16816(acc[2*ntp],   ah[0],ah[1],ah[2],ah[3], bh[ntp][0],bh[ntp][1]);
            mma16816(acc[2*ntp+1], ah[0],ah[1],ah[2],ah[3], bh[ntp][2],bh[ntp][3]);
        }
        #pragma unroll
        for (int ntp=0;ntp<4;ntp++){
            mma16816(acc[2*ntp],   ah[0],ah[1],ah[2],ah[3], bl[ntp][0],bl[ntp][1]);
            mma16816(acc[2*ntp+1], ah[0],ah[1],ah[2],ah[3], bl[ntp][2],bl[ntp][3]);
        }
        #pragma unroll
        for (int ntp=0;ntp<4;ntp++){
            mma16816(acc[2*ntp],   al[0],al[1],al[2],al[3], bh[ntp][0],bh[ntp][1]);
            mma16816(acc[2*ntp+1], al[0],al[1],al[2],al[3], bh[ntp][2],bh[ntp][3]);
        }
    }
}

// ================= SINGLE FUSED KERNEL =================
__global__ void __launch_bounds__(512) kall(
        const float* __restrict__ x,
        const float* __restrict__ W1,  const float* __restrict__ wt_w,
        const float* __restrict__ Wsa1,const float* __restrict__ Wsa2,
        const float* __restrict__ wsat_w, const float* __restrict__ wsat_b,
        const float* __restrict__ bsa1,
        const float* __restrict__ pw1, const float* __restrict__ pw2,
        const float* __restrict__ b1, const float* __restrict__ b2,
        const float* __restrict__ lng, const float* __restrict__ lnb,
        float* __restrict__ out)
{
    extern __shared__ __align__(16) char smc[];
    unsigned sb;
    asm("{ .reg .u64 t; cvta.to.shared.u64 t, %1; cvt.u32.u64 %0, t; }" : "=r"(sb) : "l"(smc));

    // small regions
    float*  sS  = (float*)smc;
    float*  sF  = (float*)(smc + 512);
    float2* sLN = (float2*)(smc + 1024);
    __nv_bfloat16* Ah = (__nv_bfloat16*)(smc + AH_OFF);
    __nv_bfloat16* Al = (__nv_bfloat16*)(smc + AL_OFF);
    // kmega work buffer aliases the A region (disjoint in time)
    float* sbuf = (float*)(smc + AH_OFF);

    __shared__ float sred[16];
    __shared__ float smom[8][10];
    __shared__ float sE[10];

    int tid  = threadIdx.x;
    int lane = tid & 31, wid = tid >> 5;
    int bk = blockIdx.x;
    int b  = bk >> 4;
    int s  = bk & 15;

    // ---------- phase 0: prep + weight image build ----------
    if (bk < 3){
        float* vec = sbuf;
        float* sp  = sbuf + 128;
        if (tid < DX) vec[tid] = (bk==0) ? wt_w[tid] : wsat_w[tid];
        __syncthreads();
        const float* W = (bk==0)?W1:(bk==1)?Wsa1:Wsa2;
        int d = tid & 127, p = tid >> 7;
        float a = 0.f;
        #pragma unroll 8
        for (int e=p*32; e<p*32+32; e++) a = fmaf(W[d*DX+e], vec[e], a);
        sp[p*DX + d] = a;
        __syncthreads();
        if (tid < DX){
            float t = (sp[tid]+sp[DX+tid]) + (sp[2*DX+tid]+sp[3*DX+tid]);
            float* dst = (bk==0)?g_v1:(bk==1)?g_u1:g_u2;
            dst[tid] = t;
        }
    } else if (bk == 3){
        if (tid < DX) sbuf[tid] = bsa1[tid]*wsat_w[tid];
        __syncthreads();
        for (int o=64;o;o>>=1){ if(tid<o) sbuf[tid]+=sbuf[tid+o]; __syncthreads(); }
        if (tid==0){ g_cconst = sbuf[0] + wsat_b[0]; g_msi=0u; g_msjc=0u; }
        if (tid < BB) g_lmax[tid] = 0u;
    } else if (bk == 4 || bk == 5){
        const float* W = (bk==4) ? pw1 : pw2;
        __nv_bfloat16* ih = (bk==4) ? g_w1hi : g_w2hi;
        __nv_bfloat16* il = (bk==4) ? g_w1lo : g_w2lo;
        for (int idx=tid; idx<16384; idx+=512){
            int k = idx & 127, n = idx >> 7;
            float v = W[k*DX + n];
            __nv_bfloat16 h = __float2bfloat16(v);
            __nv_bfloat16 l = __float2bfloat16(v - __bfloat162float(h));
            ih[n*ST + k] = h;
            il[n*ST + k] = l;
        }
    }
    gsync();

    // ---------- weight preload into smem (overlaps with phases 1-4 latency) ----------
    {
        const float4* s1 = (const float4*)g_w1hi;
        const float4* s2 = (const float4*)g_w1lo;
        const float4* s3 = (const float4*)g_w2hi;
        const float4* s4 = (const float4*)g_w2lo;
        float4* d1 = (float4*)(smc + WH1_OFF);
        float4* d2 = (float4*)(smc + WL1_OFF);
        float4* d3 = (float4*)(smc + WH2_OFF);
        float4* d4 = (float4*)(smc + WL2_OFF);
        for (int k=tid; k<IMGB/16; k+=512){ d1[k]=s1[k]; d2[k]=s2[k]; d3[k]=s3[k]; d4[k]=s4[k]; }
    }

    // ---------- phase 1: per-row dots + block logit max ----------
    {
        float4 av = ((const float4*)g_v1)[lane];
        float4 bv = ((const float4*)g_u1)[lane];
        float4 cv = ((const float4*)g_u2)[lane];
        int rowbase = bk*SLEN + wid*16;
        float lmax = -1e30f;
        #pragma unroll 2
        for (int r=0;r<16;r++){
            int row = rowbase + r;
            float4 xv = ((const float4*)x)[row*32 + lane];
            float s0 = xv.x*av.x + xv.y*av.y + xv.z*av.z + xv.w*av.w;
            float s1 = xv.x*bv.x + xv.y*bv.y + xv.z*bv.z + xv.w*bv.w;
            float s2 = xv.x*cv.x + xv.y*cv.y + xv.z*cv.z + xv.w*cv.w;
            #pragma unroll
            for (int o=16;o;o>>=1){
                s0 += __shfl_down_sync(0xffffffffu, s0, o);
                s1 += __shfl_down_sync(0xffffffffu, s1, o);
                s2 += __shfl_down_sync(0xffffffffu, s2, o);
            }
            if (lane==0){
                g_logits[row]=s0; g_d1[row]=s1; g_d2[row]=s2;
                lmax = fmaxf(lmax, s0);
            }
        }
        if (lane==0) sred[wid] = lmax;
        __syncthreads();
        if (tid==0){
            float m = sred[0];
            #pragma unroll
            for (int w=1;w<16;w++) m = fmaxf(m, sred[w]);
            atomicMax(&g_lmax[b], fkey(m));
        }
    }
    gsync();

    // ---------- phase 2: partial softmax sums ----------
    {
        float m = funkey(g_lmax[b]);
        if (tid < SLEN){
            float v = __expf(g_logits[b*LL + s*SLEN + tid] - m);
            v = wradd(v);
            if (lane==0) sred[wid] = v;
        }
        __syncthreads();
        if (tid==0){
            float t = 0.f;
            #pragma unroll
            for (int w=0;w<8;w++) t += sred[w];
            g_psum[bk] = t;
        }
    }
    gsync();

    // ---------- phase 3: si/sjc + ranges + partial sjc-moments ----------
    {
        float m = funkey(g_lmax[b]);
        float t = 0.f;
        #pragma unroll
        for (int k=0;k<SLICES;k++) t += g_psum[b*SLICES+k];
        float inv = 1.0f/t;
        float cc = g_cconst;
        if (tid < SLEN){
            int idx = b*LL + s*SLEN + tid;
            float p = __expf(g_logits[idx]-m)*inv;
            float si  = p*g_d1[idx];
            float sjc = fmaf(p, g_d2[idx], cc);
            g_si[idx]=si; g_sjc[idx]=sjc;
            float rs = fabsf(si), rj = fabsf(sjc);
            #pragma unroll
            for (int o=16;o;o>>=1){
                rs = fmaxf(rs, __shfl_xor_sync(0xffffffffu, rs, o));
                rj = fmaxf(rj, __shfl_xor_sync(0xffffffffu, rj, o));
            }
            if (lane==0){
                atomicMax(&g_msi,  __float_as_uint(rs));
                atomicMax(&g_msjc, __float_as_uint(rj));
            }
            float pw = 1.f;
            #pragma unroll
            for (int k=0;k<10;k++){
                float v = wradd(pw);
                if (lane==0) smom[wid][k]=v;
                pw *= sjc;
            }
        }
        __syncthreads();
        if (tid < 10){
            float acc = 0.f;
            #pragma unroll
            for (int w=0;w<8;w++) acc += smom[w][tid];
            g_Mpart[bk*10 + tid] = acc;
        }
    }
    gsync();

    bool pok = poly_ok();

    if (pok){
        // ---------- phase 4: invZ + partial invZ-weighted si-moments ----------
        if (tid < 10){
            float M[10];
            #pragma unroll
            for (int mi=0;mi<10;mi++){
                float acc = 0.f;
                #pragma unroll
                for (int ss=0;ss<SLICES;ss++) acc += g_Mpart[(b*SLICES+ss)*10 + mi];
                M[mi] = acc;
            }
            float e = 0.f;
            for (int mi=0; tid+mi<10; mi++)
                e = fmaf(c_P[tid+mi]*c_BIN[tid+mi][tid], M[mi], e);
            sE[tid] = e;
        }
        __syncthreads();
        if (tid < SLEN){
            int idx = b*LL + s*SLEN + tid;
            float si = g_si[idx], sjc = g_sjc[idx];
            float z = sE[9];
            #pragma unroll
            for (int k=8;k>=0;k--) z = fmaf(z, si, sE[k]);
            z -= fpoly(si + sjc);
            float w = 1.0f / z;
            g_invZ[idx] = w;
            float pw = w;
            #pragma unroll
            for (int k=0;k<10;k++){
                float v = wradd(pw);
                if (lane==0) smom[wid][k]=v;
                pw *= si;
            }
        }
        __syncthreads();
        if (tid < 10){
            float acc = 0.f;
            #pragma unroll
            for (int w=0;w<8;w++) acc += smom[w][tid];
            g_Fpart[bk*10 + tid] = acc;
        }
    } else {
        // ---------- fallback: full O(L^2) row/col sums ----------
        {
            for (int k=tid;k<LL;k+=512) sbuf[k] = g_sjc[b*LL+k];
            __syncthreads();
            int row = b*LL + s*SLEN + (tid>>1);
            int half = tid & 1;
            float si = g_si[row];
            float a = 0.f;
            for (int j=half*2048; j<half*2048+2048; j++) a += fsig(si + sbuf[j]);
            a += __shfl_xor_sync(0xffffffffu, a, 1);
            if (half==0){
                float Z = a - fsig(si + g_sjc[row]);
                g_invZ[row] = 1.0f / Z;
            }
        }
        gsync();
        {
            float* s_si = sbuf;
            float* s_wz = sbuf + 4096;
            for (int k=tid;k<LL;k+=512){ s_si[k]=g_si[b*LL+k]; s_wz[k]=g_invZ[b*LL+k]; }
            __syncthreads();
            int col = b*LL + s*SLEN + (tid>>1);
            int half = tid & 1;
            float sj = g_sjc[col];
            float a = 0.f;
            for (int i=half*2048; i<half*2048+2048; i++)
                a = fmaf(fsig(sj + s_si[i]), s_wz[i], a);
            a += __shfl_xor_sync(0xffffffffu, a, 1);
            if (half==0)
                g_S[col] = a - fsig(g_si[col] + sj) * g_invZ[col];
        }
    }
    gsync();   // Fpart/g_S complete everywhere; sbuf alias of A region retired

    // ================= FFN phase =================
    int w = wid;
    int rw = (w & 7) * 16;
    int ch = w >> 3;
    int cb = ch * 64;

    if (pok && tid < 10){
        float M[10];
        #pragma unroll
        for (int mi=0;mi<10;mi++){
            float acc = 0.f;
            #pragma unroll
            for (int ss=0;ss<SLICES;ss++) acc += g_Fpart[(b*SLICES+ss)*10 + mi];
            M[mi] = acc;
        }
        float e = 0.f;
        for (int mi=0; tid+mi<10; mi++)
            e = fmaf(c_P[tid+mi]*c_BIN[tid+mi][tid], M[mi], e);
        sF[tid] = e;
    }
    __syncthreads();

    unsigned aoff = ((lane&7) + ((lane>>3)&1)*8)*(ST*2) + (lane>>4)*16;
    unsigned boff = ((lane&7) + (lane>>4)*8)*(ST*2) + ((lane>>3)&1)*16;
    unsigned ah_base = sb + AH_OFF + rw*(ST*2) + aoff;
    unsigned al_base = sb + AL_OFF + rw*(ST*2) + aoff;
    unsigned wh1 = sb + WH1_OFF + cb*(ST*2) + boff;
    unsigned wl1 = sb + WL1_OFF + cb*(ST*2) + boff;
    unsigned wh2 = sb + WH2_OFF + cb*(ST*2) + boff;
    unsigned wl2 = sb + WL2_OFF + cb*(ST*2) + boff;

    for (int t=0; t<2; t++){
        int rowbase = bk*256 + t*128;

        if (tid < 128){
            int gr = rowbase + tid;
            float s;
            if (pok){
                float sj = g_sjc[gr];
                float v = sF[9];
                #pragma unroll
                for (int k=8;k>=0;k--) v = fmaf(v, sj, sF[k]);
                s = v - fpoly(g_si[gr] + sj) * g_invZ[gr];
            } else {
                s = g_S[gr];
            }
            sS[tid] = s;
        }
        __syncthreads();

        {
            int row = tid >> 2, q = tid & 3, cb2 = q*32;
            float s = sS[row];
            const float4* xr = (const float4*)(x + (size_t)(rowbase+row)*DX + cb2);
            #pragma unroll
            for (int g=0; g<8; g++){
                float4 a = xr[g];
                int col = cb2 + g*4;
                unsigned l0, l1;
                unsigned h0 = pack_split_hi(s*a.x, s*a.y, l0);
                unsigned h1 = pack_split_hi(s*a.z, s*a.w, l1);
                *(unsigned*)(Ah + row*ST + col)     = h0;
                *(unsigned*)(Ah + row*ST + col + 2) = h1;
                *(unsigned*)(Al + row*ST + col)     = l0;
                *(unsigned*)(Al + row*ST + col + 2) = l1;
            }
        }
        __syncthreads();

        float acc[8][4];

        mma_stage_ldm(ah_base, al_base, wh1, wl1, acc);
        __syncthreads();

        {
            int r = lane >> 2, c2 = (lane & 3)*2;
            int R0 = rw + r, R1 = R0 + 8;
            #pragma unroll
            for (int nt=0;nt<8;nt++){
                int n0 = cb + nt*8 + c2;
                float bb0 = __ldg(b1 + n0), bb1 = __ldg(b1 + n0 + 1);
                float h00 = fmaxf(acc[nt][0]+bb0, 0.f);
                float h01 = fmaxf(acc[nt][1]+bb1, 0.f);
                float h10 = fmaxf(acc[nt][2]+bb0, 0.f);
                float h11 = fmaxf(acc[nt][3]+bb1, 0.f);
                unsigned l0, l1;
                unsigned h0 = pack_split_hi(h00, h01, l0);
                unsigned h1 = pack_split_hi(h10, h11, l1);
                *(unsigned*)(Ah + R0*ST + n0) = h0;
                *(unsigned*)(Al + R0*ST + n0) = l0;
                *(unsigned*)(Ah + R1*ST + n0) = h1;
                *(unsigned*)(Al + R1*ST + n0) = l1;
            }
        }
        __syncthreads();

        mma_stage_ldm(ah_base, al_base, wh2, wl2, acc);

        {
            int r = lane >> 2, c2 = (lane & 3)*2;
            int R0 = rw + r, R1 = R0 + 8;
            float sR0 = sS[R0], sR1 = sS[R1];
            const float* x0 = x + (size_t)(rowbase+R0)*DX;
            const float* x1 = x + (size_t)(rowbase+R1)*DX;
            float s0=0.f, q0=0.f, s1=0.f, q1=0.f;
            #pragma unroll
            for (int nt=0;nt<8;nt++){
                int n0 = cb + nt*8 + c2;
                float bb0 = __ldg(b2 + n0), bb1 = __ldg(b2 + n0 + 1);
                float2 xa = *(const float2*)(x0 + n0);
                float2 xb = *(const float2*)(x1 + n0);
                float y00 = acc[nt][0] + bb0 + sR0*xa.x;
                float y01 = acc[nt][1] + bb1 + sR0*xa.y;
                float y10 = acc[nt][2] + bb0 + sR1*xb.x;
                float y11 = acc[nt][3] + bb1 + sR1*xb.y;
                acc[nt][0]=y00; acc[nt][1]=y01; acc[nt][2]=y10; acc[nt][3]=y11;
                s0 += y00+y01; q0 += y00*y00+y01*y01;
                s1 += y10+y11; q1 += y10*y10+y11*y11;
            }
            #pragma unroll
            for (int o=1;o<4;o<<=1){
                s0 += __shfl_xor_sync(0xffffffffu, s0, o);
                q0 += __shfl_xor_sync(0xffffffffu, q0, o);
                s1 += __shfl_xor_sync(0xffffffffu, s1, o);
                q1 += __shfl_xor_sync(0xffffffffu, q1, o);
            }
            if ((lane & 3) == 0){
                sLN[R0*2 + ch] = make_float2(s0, q0);
                sLN[R1*2 + ch] = make_float2(s1, q1);
            }
            __syncthreads();
            float2 o0 = sLN[R0*2 + (ch^1)];
            float2 o1 = sLN[R1*2 + (ch^1)];
            s0 += o0.x; q0 += o0.y;
            s1 += o1.x; q1 += o1.y;
            float mu0  = s0 * (1.0f/128.0f);
            float inv0 = rsqrtf(q0*(1.0f/128.0f) - mu0*mu0 + 1e-6f);
            float mu1  = s1 * (1.0f/128.0f);
            float inv1 = rsqrtf(q1*(1.0f/128.0f) - mu1*mu1 + 1e-6f);
            float* p0 = out + (size_t)(rowbase+R0)*DX;
            float* p1 = out + (size_t)(rowbase+R1)*DX;
            #pragma unroll
            for (int nt=0;nt<8;nt++){
                int n0 = cb + nt*8 + c2;
                float2 gg = *(const float2*)(lng + n0);
                float2 be = *(const float2*)(lnb + n0);
                float2 v0, v1;
                v0.x = (acc[nt][0]-mu0)*inv0*gg.x + be.x;
                v0.y = (acc[nt][1]-mu0)*inv0*gg.y + be.y;
                v1.x = (acc[nt][2]-mu1)*inv1*gg.x + be.x;
                v1.y = (acc[nt][3]-mu1)*inv1*gg.y + be.y;
                *(float2*)(p0 + n0) = v0;
                *(float2*)(p1 + n0) = v1;
            }
        }
        __syncthreads();
    }
}

// ---------------- launch ----------------
extern "C" void kernel_launch(void* const* d_in, const int* in_sizes, int n_in,
                              void* d_out, int out_size)
{
    const float* x     = (const float*)d_in[0];
    const float* W1    = (const float*)d_in[2];
    const float* wt_w  = (const float*)d_in[4];
    const float* Wsa1  = (const float*)d_in[6];
    const float* Wsa2  = (const float*)d_in[7];
    const float* wsatw = (const float*)d_in[8];
    const float* wsatb = (const float*)d_in[9];
    const float* bsa1  = (const float*)d_in[10];
    const float* pw1   = (const float*)d_in[11];
    const float* pb1   = (const float*)d_in[12];
    const float* pw2   = (const float*)d_in[13];
    const float* pb2   = (const float*)d_in[14];
    const float* lng   = (const float*)d_in[15];
    const float* lnb   = (const float*)d_in[16];
    float* out = (float*)d_out;

    cudaFuncSetAttribute(kall, cudaFuncAttributeMaxDynamicSharedMemorySize, KSMEM);
    kall<<<GRIDN,512,KSMEM>>>(x, W1, wt_w, Wsa1, Wsa2, wsatw, wsatb, bsa1,
                              pw1, pw2, pb1, pb2, lng, lnb, out);
}